// round 1
// baseline (speedup 1.0000x reference)
#include <cuda_runtime.h>
#include <cuda_bf16.h>
#include <math.h>

// ---------------- problem constants ----------------
#define DIM     48
#define QKVC    144          // 3*DIM
#define H_IMG   256
#define W_IMG   256
#define HW      65536        // 256*256
#define NH      8            // heads
#define HC      96           // channels per head (768/8)
#define OHW     66           // unfold output grid (66x66)
#define NP      4356         // 66*66 patches
#define KS      4            // unfold kernel/stride
#define PADU    4            // unfold pad

// ---------------- scratch (static device globals; no allocations) ----------
__device__ float g_qkv [QKVC * HW];        // after 1x1 qkv proj
__device__ float g_dw  [QKVC * HW];        // after depthwise 3x3
__device__ float g_q   [NH * HC * NP];     // unfolded + (later) normalized Q
__device__ float g_k   [NH * HC * NP];
__device__ float g_v   [NH * HC * NP];     // unfolded V (scaled in place by 1/rowsum)
__device__ float g_S   [(size_t)NH * NP * NP];   // 607 MB score / exp matrix
__device__ float g_rowsum[NH * NP];
__device__ float g_o   [NH * HC * NP];     // attention output per head
__device__ float g_fold[DIM * HW];         // folded image before final proj

// ================= 1) qkv 1x1 projection ====================================
// qkv[o, p] = sum_c w_qkv[o*48+c] * x[c*HW + p]
__global__ __launch_bounds__(256) void k_qkv_proj(const float* __restrict__ x,
                                                  const float* __restrict__ w) {
    __shared__ float xs[DIM][256];
    int t = threadIdx.x;
    int p0 = blockIdx.x * 256;
#pragma unroll
    for (int c = 0; c < DIM; c++) xs[c][t] = x[c * HW + p0 + t];
    __syncthreads();
    for (int o = 0; o < QKVC; o++) {
        float acc = 0.f;
#pragma unroll
        for (int c = 0; c < DIM; c++) acc += __ldg(&w[o * DIM + c]) * xs[c][t];
        g_qkv[o * HW + p0 + t] = acc;
    }
}

// ================= 2) depthwise 3x3, pad 1 (correlation, XLA convention) ====
__global__ __launch_bounds__(256) void k_dwconv(const float* __restrict__ wdw) {
    int idx = blockIdx.x * 256 + threadIdx.x;          // over QKVC*HW
    int ch = idx >> 16;
    int p  = idx & 65535;
    int y = p >> 8, x = p & 255;
    const float* wv = wdw + ch * 9;
    const float* in = g_qkv + ch * HW;
    float acc = 0.f;
#pragma unroll
    for (int di = 0; di < 3; di++) {
        int yy = y + di - 1;
        if ((unsigned)yy >= H_IMG) continue;
#pragma unroll
        for (int dj = 0; dj < 3; dj++) {
            int xx = x + dj - 1;
            if ((unsigned)xx >= W_IMG) continue;
            acc += wv[di * 3 + dj] * in[yy * W_IMG + xx];
        }
    }
    g_dw[idx] = acc;
}

// ================= 3) unfold + head split for q,k,v =========================
// dst[h][cd][n]; row = h*96+cd; c = row/16; kk = row%16 (ki*4+kj);
// n = i*66+j -> src pixel (4i+ki-4, 4j+kj-4), 0 outside.
__global__ __launch_bounds__(256) void k_unfold() {
    int idx = blockIdx.x * 256 + threadIdx.x;   // over 3*NH*HC*NP (exact)
    const int per = NH * HC * NP;
    int which = idx / per;
    int t = idx - which * per;
    int n = t % NP;
    int cd = (t / NP) % HC;
    int h = t / (HC * NP);
    int row = h * HC + cd;
    int c = row >> 4;
    int kk = row & 15;
    int ki = kk >> 2, kj = kk & 3;
    int i = n / OHW, j = n - i * OHW;
    int y = 4 * i + ki - PADU;
    int x = 4 * j + kj - PADU;
    float val = 0.f;
    if ((unsigned)y < H_IMG && (unsigned)x < W_IMG)
        val = g_dw[(which * DIM + c) * HW + y * W_IMG + x];
    float* dst = (which == 0) ? g_q : (which == 1) ? g_k : g_v;
    dst[t] = val;
}

// ================= 4) L2 norm of q,k along channel dim (in place) ===========
__global__ __launch_bounds__(256) void k_l2norm() {
    int idx = blockIdx.x * 256 + threadIdx.x;   // over 2*NH*NP
    if (idx >= 2 * NH * NP) return;
    int which = idx / (NH * NP);
    int t = idx - which * (NH * NP);
    int h = t / NP;
    int n = t - h * NP;
    float* base = ((which == 0) ? g_q : g_k) + (size_t)h * HC * NP + n;
    float ss = 0.f;
#pragma unroll 8
    for (int cd = 0; cd < HC; cd++) { float v = base[cd * NP]; ss += v * v; }
    float nrm = sqrtf(ss);
    float s = 1.f / fmaxf(nrm, 1e-12f);
#pragma unroll 8
    for (int cd = 0; cd < HC; cd++) base[cd * NP] *= s;
}

// ================= 5) S = temp * Q^T K  (per head) ==========================
// S[n,m] = temp[h] * sum_cd Q[cd,n] * K[cd,m].  128x128 tile, 8x8 per thread.
__global__ __launch_bounds__(256) void k_gemm_qk(const float* __restrict__ temp) {
    int h = blockIdx.z;
    const float* Qh = g_q + (size_t)h * HC * NP;
    const float* Kh = g_k + (size_t)h * HC * NP;
    float* Sh = g_S + (size_t)h * NP * NP;
    __shared__ float Qs[16][128];
    __shared__ float Ks[16][128];
    int n0 = blockIdx.x * 128, m0 = blockIdx.y * 128;
    int tid = threadIdx.x;
    int tx = tid & 15, ty = tid >> 4;
    float acc[8][8];
#pragma unroll
    for (int i = 0; i < 8; i++)
#pragma unroll
        for (int j = 0; j < 8; j++) acc[i][j] = 0.f;

    for (int k0 = 0; k0 < HC; k0 += 16) {
#pragma unroll
        for (int l = 0; l < 8; l++) {
            int idx = tid + l * 256;
            int kk = idx >> 7, cc = idx & 127;
            int n = n0 + cc;
            Qs[kk][cc] = (n < NP) ? Qh[(k0 + kk) * NP + n] : 0.f;
            int m = m0 + cc;
            Ks[kk][cc] = (m < NP) ? Kh[(k0 + kk) * NP + m] : 0.f;
        }
        __syncthreads();
#pragma unroll
        for (int kk = 0; kk < 16; kk++) {
            float a[8], b[8];
#pragma unroll
            for (int i = 0; i < 8; i++) a[i] = Qs[kk][ty + i * 16];
#pragma unroll
            for (int j = 0; j < 8; j++) b[j] = Ks[kk][tx + j * 16];
#pragma unroll
            for (int i = 0; i < 8; i++)
#pragma unroll
                for (int j = 0; j < 8; j++) acc[i][j] = fmaf(a[i], b[j], acc[i][j]);
        }
        __syncthreads();
    }
    float tmp = __ldg(&temp[h]);
#pragma unroll
    for (int i = 0; i < 8; i++) {
        int n = n0 + ty + i * 16;
        if (n >= NP) continue;
        float* rowp = Sh + (size_t)n * NP;
#pragma unroll
        for (int j = 0; j < 8; j++) {
            int m = m0 + tx + j * 16;
            if (m < NP) rowp[m] = acc[i][j] * tmp;
        }
    }
}

// ================= 6) rowwise softmax numerator: E = exp(S - rowmax) ========
// stores unnormalized exp in place + rowsum per (h,n).  Normalization is
// folded into V (scale V columns by 1/rowsum before GEMM2).
__global__ __launch_bounds__(256) void k_softmax() {
    int row = blockIdx.x;                       // over NH*NP
    float* r = g_S + (size_t)row * NP;
    int tid = threadIdx.x;
    __shared__ float red[256];
    float mx = -INFINITY;
    for (int m = tid; m < NP; m += 256) mx = fmaxf(mx, r[m]);
    red[tid] = mx; __syncthreads();
    for (int s = 128; s > 0; s >>= 1) {
        if (tid < s) red[tid] = fmaxf(red[tid], red[tid + s]);
        __syncthreads();
    }
    mx = red[0]; __syncthreads();
    float sum = 0.f;
    for (int m = tid; m < NP; m += 256) {
        float e = __expf(r[m] - mx);
        r[m] = e;
        sum += e;
    }
    red[tid] = sum; __syncthreads();
    for (int s = 128; s > 0; s >>= 1) {
        if (tid < s) red[tid] += red[tid + s];
        __syncthreads();
    }
    if (tid == 0) g_rowsum[row] = red[0];
}

// ================= 7) V[h][c][n] /= rowsum[h][n]  (in place) ================
__global__ __launch_bounds__(256) void k_vscale() {
    int idx = blockIdx.x * 256 + threadIdx.x;   // over NH*HC*NP (exact)
    int n = idx % NP;
    int h = idx / (HC * NP);
    g_v[idx] = g_v[idx] / g_rowsum[h * NP + n];
}

// ================= 8) out = Vs @ E  (per head) ==============================
// out[c,m] = sum_n Vs[c,n] * E[n,m].  M=96 full, Ntile=64, Ktile=32,
// 256 threads, 6x4 per thread.
__global__ __launch_bounds__(256) void k_gemm_av() {
    int h = blockIdx.y;
    const float* Vh = g_v + (size_t)h * HC * NP;
    const float* Eh = g_S + (size_t)h * NP * NP;
    float* Oh = g_o + (size_t)h * HC * NP;
    __shared__ float As[32][HC + 1];   // [kk][c], padded against bank conflicts
    __shared__ float Bs[32][64];
    int m0 = blockIdx.x * 64;
    int tid = threadIdx.x;
    int tx = tid & 15, ty = tid >> 4;   // tx -> m (4), ty -> c (6)
    float acc[6][4];
#pragma unroll
    for (int i = 0; i < 6; i++)
#pragma unroll
        for (int j = 0; j < 4; j++) acc[i][j] = 0.f;

    for (int n0 = 0; n0 < NP; n0 += 32) {
#pragma unroll
        for (int l = 0; l < 12; l++) {           // 32*96 = 3072 elems
            int idx = tid + l * 256;
            int c = idx >> 5, kk = idx & 31;
            int n = n0 + kk;
            As[kk][c] = (n < NP) ? Vh[(size_t)c * NP + n] : 0.f;
        }
#pragma unroll
        for (int l = 0; l < 8; l++) {            // 32*64 = 2048 elems
            int idx = tid + l * 256;
            int kk = idx >> 6, mm = idx & 63;
            int n = n0 + kk, m = m0 + mm;
            Bs[kk][mm] = (n < NP && m < NP) ? Eh[(size_t)n * NP + m] : 0.f;
        }
        __syncthreads();
#pragma unroll
        for (int kk = 0; kk < 32; kk++) {
            float a[6], b[4];
#pragma unroll
            for (int i = 0; i < 6; i++) a[i] = As[kk][ty + i * 16];
#pragma unroll
            for (int j = 0; j < 4; j++) b[j] = Bs[kk][tx + j * 16];
#pragma unroll
            for (int i = 0; i < 6; i++)
#pragma unroll
                for (int j = 0; j < 4; j++) acc[i][j] = fmaf(a[i], b[j], acc[i][j]);
        }
        __syncthreads();
    }
#pragma unroll
    for (int i = 0; i < 6; i++) {
        int c = ty + i * 16;                     // always < 96
        float* rowp = Oh + (size_t)c * NP;
#pragma unroll
        for (int j = 0; j < 4; j++) {
            int m = m0 + tx + j * 16;
            if (m < NP) rowp[m] = acc[i][j];
        }
    }
}

// ================= 9) fold (pure permutation; stride==ksize => no overlap) ==
__global__ __launch_bounds__(256) void k_fold() {
    int idx = blockIdx.x * 256 + threadIdx.x;   // over DIM*HW (exact)
    int c = idx >> 16;
    int p = idx & 65535;
    int y = p >> 8, x = p & 255;
    int ki = y & 3, kj = x & 3;
    int i = (y + PADU) >> 2;
    int j = (x + PADU) >> 2;
    int n = i * OHW + j;
    int row = c * 16 + ki * 4 + kj;
    int h = row / HC;
    int cd = row - h * HC;
    g_fold[idx] = g_o[((size_t)h * HC + cd) * NP + n];
}

// ================= 10) final 1x1 projection =================================
__global__ __launch_bounds__(256) void k_proj(const float* __restrict__ w,
                                              float* __restrict__ out) {
    __shared__ float xs[DIM][256];
    int t = threadIdx.x;
    int p0 = blockIdx.x * 256;
#pragma unroll
    for (int c = 0; c < DIM; c++) xs[c][t] = g_fold[c * HW + p0 + t];
    __syncthreads();
    for (int o = 0; o < DIM; o++) {
        float acc = 0.f;
#pragma unroll
        for (int c = 0; c < DIM; c++) acc += __ldg(&w[o * DIM + c]) * xs[c][t];
        out[o * HW + p0 + t] = acc;
    }
}

// ============================================================================
extern "C" void kernel_launch(void* const* d_in, const int* in_sizes, int n_in,
                              void* d_out, int out_size) {
    const float* x      = (const float*)d_in[0];   // (1,48,256,256)
    const float* w_qkv  = (const float*)d_in[1];   // (144,48)
    const float* w_dw   = (const float*)d_in[2];   // (144,1,3,3)
    const float* temp   = (const float*)d_in[3];   // (8,1,1)
    const float* w_proj = (const float*)d_in[4];   // (48,48)
    float* out = (float*)d_out;

    k_qkv_proj<<<HW / 256, 256>>>(x, w_qkv);
    k_dwconv<<<(QKVC * HW) / 256, 256>>>(w_dw);
    k_unfold<<<(3 * NH * HC * NP) / 256, 256>>>();
    k_l2norm<<<(2 * NH * NP + 255) / 256, 256>>>();
    {
        dim3 grid((NP + 127) / 128, (NP + 127) / 128, NH);
        k_gemm_qk<<<grid, 256>>>(temp);
    }
    k_softmax<<<NH * NP, 256>>>();
    k_vscale<<<(NH * HC * NP) / 256, 256>>>();
    {
        dim3 grid((NP + 63) / 64, NH);
        k_gemm_av<<<grid, 256>>>();
    }
    k_fold<<<(DIM * HW) / 256, 256>>>();
    k_proj<<<HW / 256, 256>>>(w_proj, out);
}

// round 2
// speedup vs baseline: 3.7976x; 3.7976x over previous
#include <cuda_runtime.h>
#include <cuda_fp16.h>
#include <math.h>

// ---------------- problem constants ----------------
#define DIM     48
#define QKVC    144          // 3*DIM
#define H_IMG   256
#define W_IMG   256
#define HW      65536
#define NH      8
#define HC      96           // channels per head
#define OHW     66
#define NP      4356         // 66*66 patches
#define NPP     4480         // padded to 35*128
#define PADU    4
#define LOG2E   1.44269504f
#define VGAIN   2048.0f      // keeps Vs=C*v/rowsum in fp16 normal range

// ---------------- scratch ----------------
__device__ float  g_qkv [QKVC * HW];
__device__ float  g_dw  [QKVC * HW];
__device__ float  g_qn  [NH * NP * HC];     // q unfolded, [h][n][c] fp32
__device__ float  g_kn  [NH * NP * HC];
__device__ float  g_v   [NH * HC * NPP];    // v unfolded, [h][c][n] fp32 (pad 0)
__device__ __align__(16) __half g_qt[NH * NPP * HC];   // normalized q, [h][n][c]
__device__ __align__(16) __half g_kt[NH * NPP * HC];
__device__ __align__(16) __half g_vh[NH * HC * NPP];   // Vs = C*v/rowsum
__device__ __align__(16) __half g_E [(size_t)NH * NPP * NPP]; // E^T: [h][m][n]
__device__ float  g_rowsum[NH * NPP];
__device__ float  g_o   [NH * HC * NPP];    // attention out [h][c][m]
__device__ float  g_fold[DIM * HW];

// ================= 1) qkv 1x1 projection ===================================
__global__ __launch_bounds__(256) void k_qkv_proj(const float* __restrict__ x,
                                                  const float* __restrict__ w) {
    __shared__ float xs[DIM][256];
    int t = threadIdx.x;
    int p0 = blockIdx.x * 256;
#pragma unroll
    for (int c = 0; c < DIM; c++) xs[c][t] = x[c * HW + p0 + t];
    __syncthreads();
    for (int o = 0; o < QKVC; o++) {
        float acc = 0.f;
#pragma unroll
        for (int c = 0; c < DIM; c++) acc += __ldg(&w[o * DIM + c]) * xs[c][t];
        g_qkv[o * HW + p0 + t] = acc;
    }
}

// ================= 2) depthwise 3x3 ========================================
__global__ __launch_bounds__(256) void k_dwconv(const float* __restrict__ wdw) {
    int idx = blockIdx.x * 256 + threadIdx.x;
    int ch = idx >> 16;
    int p  = idx & 65535;
    int y = p >> 8, x = p & 255;
    const float* wv = wdw + ch * 9;
    const float* in = g_qkv + ch * HW;
    float acc = 0.f;
#pragma unroll
    for (int di = 0; di < 3; di++) {
        int yy = y + di - 1;
        if ((unsigned)yy >= H_IMG) continue;
#pragma unroll
        for (int dj = 0; dj < 3; dj++) {
            int xx = x + dj - 1;
            if ((unsigned)xx >= W_IMG) continue;
            acc += wv[di * 3 + dj] * in[yy * W_IMG + xx];
        }
    }
    g_dw[idx] = acc;
}

// ================= 3a) unfold q,k to [h][n][c] fp32 ========================
__global__ __launch_bounds__(256) void k_unfold_qk() {
    int t = blockIdx.x * 256 + threadIdx.x;  // over 2*NH*NP*HC (exact)
    int cd = t % HC;
    int r  = t / HC;
    int n  = r % NP;
    int r2 = r / NP;
    int h  = r2 & 7;
    int which = r2 >> 3;
    int row = h * HC + cd;
    int c  = row >> 4;
    int kk = row & 15;
    int ki = kk >> 2, kj = kk & 3;
    int i = n / OHW, j = n - i * OHW;
    int y = 4 * i + ki - PADU;
    int x = 4 * j + kj - PADU;
    float val = 0.f;
    if ((unsigned)y < H_IMG && (unsigned)x < W_IMG)
        val = g_dw[(which * DIM + c) * HW + y * W_IMG + x];
    float* dst = (which == 0) ? g_qn : g_kn;
    dst[(h * NP + n) * HC + cd] = val;
}

// ================= 3b) unfold v to [h][c][n-padded] fp32 ===================
__global__ __launch_bounds__(256) void k_unfold_v() {
    int t = blockIdx.x * 256 + threadIdx.x;  // over NH*HC*NP (exact)
    int n  = t % NP;
    int r  = t / NP;
    int cd = r % HC;
    int h  = r / HC;
    int row = h * HC + cd;
    int c  = row >> 4;
    int kk = row & 15;
    int ki = kk >> 2, kj = kk & 3;
    int i = n / OHW, j = n - i * OHW;
    int y = 4 * i + ki - PADU;
    int x = 4 * j + kj - PADU;
    float val = 0.f;
    if ((unsigned)y >= H_IMG || (unsigned)x >= W_IMG) val = 0.f;
    else val = g_dw[(2 * DIM + c) * HW + y * W_IMG + x];
    g_v[(h * HC + cd) * NPP + n] = val;
}

// ================= 4) L2-normalize q,k -> fp16 [h][n][c] ===================
// one warp per (which,h,n) row; lanes cover 96 channels (3 each)
__global__ __launch_bounds__(256) void k_l2norm() {
    int warp = blockIdx.x * 8 + (threadIdx.x >> 5);   // over 2*NH*NP
    int lane = threadIdx.x & 31;
    int n = warp % NP;
    int r = warp / NP;
    int h = r & 7;
    int which = r >> 3;
    const float* src = ((which == 0) ? g_qn : g_kn) + (h * NP + n) * HC;
    float v0 = src[lane], v1 = src[lane + 32], v2 = src[lane + 64];
    float ss = v0 * v0 + v1 * v1 + v2 * v2;
#pragma unroll
    for (int o = 16; o > 0; o >>= 1) ss += __shfl_xor_sync(0xffffffffu, ss, o);
    float s = 1.f / fmaxf(sqrtf(ss), 1e-12f);
    __half* dst = ((which == 0) ? g_qt : g_kt) + ((size_t)h * NPP + n) * HC;
    dst[lane]      = __float2half_rn(v0 * s);
    dst[lane + 32] = __float2half_rn(v1 * s);
    dst[lane + 64] = __float2half_rn(v2 * s);
}

// ================= 5a) zero rowsums ========================================
__global__ __launch_bounds__(256) void k_zero_rowsum() {
    int i = blockIdx.x * 256 + threadIdx.x;   // 8*NPP = 35840 exact
    g_rowsum[i] = 0.f;
}

// ================= 5b) GEMM1: E^T[m][n] = exp(t*(K_m . Q_n) - |t|) =========
// A = Kt rows (m), B = Qt rows (n), both row-major fp16 with K=96 contiguous.
// block tile 128(m) x 128(n), 8 warps = 2(m) x 4(n), warp tile 64x32.
// fused epilogue: exp2, stage tile in smem, coalesced fp16 write of E^T,
// column sums (over m<NP) atomically added to g_rowsum[n].
#define SA1 104    // smem row stride (halves) for A/B tiles
#define SE1 136    // smem row stride for staged E tile
__global__ __launch_bounds__(256) void k_gemm_qk(const float* __restrict__ temp) {
    extern __shared__ __half sm[];
    __half* As = sm;                 // [128][SA1]
    __half* Bs = sm + 128 * SA1;     // [128][SA1]
    int h = blockIdx.z;
    const __half* A = g_kt + (size_t)h * NPP * HC;
    const __half* B = g_qt + (size_t)h * NPP * HC;
    int bm0 = blockIdx.y * 128;
    int bn0 = blockIdx.x * 128;
    int tid = threadIdx.x;

    // load full K=96 tiles (128 rows x 96 halves each, 16B vectors)
#pragma unroll
    for (int l = 0; l < 6; l++) {
        int v = tid + l * 256;          // < 1536
        int r = v / 12, c = v % 12;
        reinterpret_cast<uint4*>(&As[r * SA1])[c] =
            reinterpret_cast<const uint4*>(A + (size_t)(bm0 + r) * HC)[c];
        reinterpret_cast<uint4*>(&Bs[r * SA1])[c] =
            reinterpret_cast<const uint4*>(B + (size_t)(bn0 + r) * HC)[c];
    }
    __syncthreads();

    int warp = tid >> 5, lane = tid & 31;
    int wm = warp >> 2, wn = warp & 3;      // 2 x 4
    int g = lane >> 3, rr = lane & 7;

    float acc[4][4][4];
#pragma unroll
    for (int i = 0; i < 4; i++)
#pragma unroll
        for (int j = 0; j < 4; j++)
#pragma unroll
            for (int q = 0; q < 4; q++) acc[i][j][q] = 0.f;

    unsigned sA = (unsigned)__cvta_generic_to_shared(As);
    unsigned sB = (unsigned)__cvta_generic_to_shared(Bs);

#pragma unroll
    for (int kk = 0; kk < 6; kk++) {
        unsigned a[4][4], b[4][2];
#pragma unroll
        for (int i = 0; i < 4; i++) {
            int row = wm * 64 + i * 16 + rr + (g & 1) * 8;
            int ko  = kk * 16 + (g >> 1) * 8;
            unsigned ad = sA + (row * SA1 + ko) * 2;
            asm volatile("ldmatrix.sync.aligned.m8n8.x4.shared.b16 {%0,%1,%2,%3}, [%4];"
                         : "=r"(a[i][0]), "=r"(a[i][1]), "=r"(a[i][2]), "=r"(a[i][3])
                         : "r"(ad));
        }
#pragma unroll
        for (int jp = 0; jp < 2; jp++) {
            int col = wn * 32 + (jp * 2 + (g >> 1)) * 8 + rr;
            int ko  = kk * 16 + (g & 1) * 8;
            unsigned ad = sB + (col * SA1 + ko) * 2;
            asm volatile("ldmatrix.sync.aligned.m8n8.x4.shared.b16 {%0,%1,%2,%3}, [%4];"
                         : "=r"(b[jp * 2][0]), "=r"(b[jp * 2][1]),
                           "=r"(b[jp * 2 + 1][0]), "=r"(b[jp * 2 + 1][1])
                         : "r"(ad));
        }
#pragma unroll
        for (int i = 0; i < 4; i++)
#pragma unroll
            for (int j = 0; j < 4; j++) {
                asm volatile(
                    "mma.sync.aligned.m16n8k16.row.col.f32.f16.f16.f32 "
                    "{%0,%1,%2,%3},{%4,%5,%6,%7},{%8,%9},{%0,%1,%2,%3};"
                    : "+f"(acc[i][j][0]), "+f"(acc[i][j][1]),
                      "+f"(acc[i][j][2]), "+f"(acc[i][j][3])
                    : "r"(a[i][0]), "r"(a[i][1]), "r"(a[i][2]), "r"(a[i][3]),
                      "r"(b[j][0]), "r"(b[j][1]));
            }
    }
    __syncthreads();   // done with As/Bs; reuse smem for staged E tile

    float t  = __ldg(&temp[h]);
    float tl = t * LOG2E;
    float ab = fabsf(t) * LOG2E;

    __half* Es = sm;   // [128][SE1]
#pragma unroll
    for (int i = 0; i < 4; i++) {
        int r0 = wm * 64 + i * 16 + (lane >> 2);
#pragma unroll
        for (int j = 0; j < 4; j++) {
            int c0 = wn * 32 + j * 8 + 2 * (lane & 3);
            float e0 = exp2f(acc[i][j][0] * tl - ab);
            float e1 = exp2f(acc[i][j][1] * tl - ab);
            float e2 = exp2f(acc[i][j][2] * tl - ab);
            float e3 = exp2f(acc[i][j][3] * tl - ab);
            *reinterpret_cast<__half2*>(&Es[r0 * SE1 + c0]) = __floats2half2_rn(e0, e1);
            *reinterpret_cast<__half2*>(&Es[(r0 + 8) * SE1 + c0]) = __floats2half2_rn(e2, e3);
        }
    }
    __syncthreads();

    // coalesced write of E^T tile
    __half* Eh = g_E + (size_t)h * NPP * NPP;
#pragma unroll
    for (int l = 0; l < 8; l++) {
        int v = tid + l * 256;          // < 2048
        int r = v >> 4, c8 = v & 15;
        reinterpret_cast<uint4*>(Eh + (size_t)(bm0 + r) * NPP + bn0)[c8] =
            reinterpret_cast<uint4*>(&Es[r * SE1])[c8];
    }

    // rowsum over valid m for each column n
    int mlim = NP - bm0; if (mlim > 128) mlim = 128;
    if (tid < 128) {
        float s = 0.f;
        for (int m = 0; m < mlim; m++) s += __half2float(Es[m * SE1 + tid]);
        atomicAdd(&g_rowsum[h * NPP + bn0 + tid], s);
    }
}

// ================= 6) Vs = VGAIN * v / rowsum  -> fp16 =====================
__global__ __launch_bounds__(256) void k_vscale() {
    int t = blockIdx.x * 256 + threadIdx.x;  // over NH*HC*NP (exact)
    int n  = t % NP;
    int r  = t / NP;
    int cd = r % HC;
    int h  = r / HC;
    size_t idx = (size_t)(h * HC + cd) * NPP + n;
    float val = g_v[idx] * VGAIN / g_rowsum[h * NPP + n];
    g_vh[idx] = __float2half_rn(val);
}

// ================= 7) GEMM2: out[c][m] = (1/C) sum_n Vs[c][n] E^T[m][n] ====
// A = Vs rows (c, 96), B = E^T rows (m), k = n.  Block tile 96 x 64,
// k-chunk 64, 8 warps = 2(c:48) x 4(m:16), warp tile 48x16.
#define SA2 72
__global__ __launch_bounds__(256) void k_gemm_av() {
    __shared__ __half As[96 * SA2];
    __shared__ __half Bs[64 * SA2];
    int h = blockIdx.y;
    const __half* A = g_vh + (size_t)h * HC * NPP;
    const __half* B = g_E  + (size_t)h * NPP * NPP;
    int bm0 = blockIdx.x * 64;                 // output m range
    int tid = threadIdx.x;
    int warp = tid >> 5, lane = tid & 31;
    int wm = warp >> 2, wn = warp & 3;
    int g = lane >> 3, rr = lane & 7;

    float acc[3][2][4];
#pragma unroll
    for (int i = 0; i < 3; i++)
#pragma unroll
        for (int j = 0; j < 2; j++)
#pragma unroll
            for (int q = 0; q < 4; q++) acc[i][j][q] = 0.f;

    unsigned sA = (unsigned)__cvta_generic_to_shared(As);
    unsigned sB = (unsigned)__cvta_generic_to_shared(Bs);

    for (int n0 = 0; n0 < NPP; n0 += 64) {
#pragma unroll
        for (int l = 0; l < 3; l++) {
            int v = tid + l * 256;            // < 768
            int r = v >> 3, c8 = v & 7;
            reinterpret_cast<uint4*>(&As[r * SA2])[c8] =
                reinterpret_cast<const uint4*>(A + (size_t)r * NPP + n0)[c8];
        }
#pragma unroll
        for (int l = 0; l < 2; l++) {
            int v = tid + l * 256;            // < 512
            int r = v >> 3, c8 = v & 7;
            reinterpret_cast<uint4*>(&Bs[r * SA2])[c8] =
                reinterpret_cast<const uint4*>(B + (size_t)(bm0 + r) * NPP + n0)[c8];
        }
        __syncthreads();

#pragma unroll
        for (int kk = 0; kk < 4; kk++) {
            unsigned a[3][4], b[2][2];
#pragma unroll
            for (int i = 0; i < 3; i++) {
                int row = wm * 48 + i * 16 + rr + (g & 1) * 8;
                int ko  = kk * 16 + (g >> 1) * 8;
                unsigned ad = sA + (row * SA2 + ko) * 2;
                asm volatile("ldmatrix.sync.aligned.m8n8.x4.shared.b16 {%0,%1,%2,%3}, [%4];"
                             : "=r"(a[i][0]), "=r"(a[i][1]), "=r"(a[i][2]), "=r"(a[i][3])
                             : "r"(ad));
            }
            {
                int col = wn * 16 + (g >> 1) * 8 + rr;
                int ko  = kk * 16 + (g & 1) * 8;
                unsigned ad = sB + (col * SA2 + ko) * 2;
                asm volatile("ldmatrix.sync.aligned.m8n8.x4.shared.b16 {%0,%1,%2,%3}, [%4];"
                             : "=r"(b[0][0]), "=r"(b[0][1]), "=r"(b[1][0]), "=r"(b[1][1])
                             : "r"(ad));
            }
#pragma unroll
            for (int i = 0; i < 3; i++)
#pragma unroll
                for (int j = 0; j < 2; j++) {
                    asm volatile(
                        "mma.sync.aligned.m16n8k16.row.col.f32.f16.f16.f32 "
                        "{%0,%1,%2,%3},{%4,%5,%6,%7},{%8,%9},{%0,%1,%2,%3};"
                        : "+f"(acc[i][j][0]), "+f"(acc[i][j][1]),
                          "+f"(acc[i][j][2]), "+f"(acc[i][j][3])
                        : "r"(a[i][0]), "r"(a[i][1]), "r"(a[i][2]), "r"(a[i][3]),
                          "r"(b[j][0]), "r"(b[j][1]));
                }
        }
        __syncthreads();
    }

    const float invC = 1.0f / VGAIN;
    float* O = g_o + (size_t)h * HC * NPP;
#pragma unroll
    for (int i = 0; i < 3; i++) {
        int c0 = wm * 48 + i * 16 + (lane >> 2);
#pragma unroll
        for (int j = 0; j < 2; j++) {
            int m0 = bm0 + wn * 16 + j * 8 + 2 * (lane & 3);
            O[(size_t)c0 * NPP + m0]           = acc[i][j][0] * invC;
            O[(size_t)c0 * NPP + m0 + 1]       = acc[i][j][1] * invC;
            O[(size_t)(c0 + 8) * NPP + m0]     = acc[i][j][2] * invC;
            O[(size_t)(c0 + 8) * NPP + m0 + 1] = acc[i][j][3] * invC;
        }
    }
}

// ================= 8) fold (pure permutation) ==============================
__global__ __launch_bounds__(256) void k_fold() {
    int idx = blockIdx.x * 256 + threadIdx.x;   // DIM*HW exact
    int c = idx >> 16;
    int p = idx & 65535;
    int y = p >> 8, x = p & 255;
    int ki = y & 3, kj = x & 3;
    int i = (y + PADU) >> 2;
    int j = (x + PADU) >> 2;
    int n = i * OHW + j;
    int row = c * 16 + ki * 4 + kj;
    int h = row / HC;
    int cd = row - h * HC;
    g_fold[idx] = g_o[(size_t)(h * HC + cd) * NPP + n];
}

// ================= 9) final 1x1 projection =================================
__global__ __launch_bounds__(256) void k_proj(const float* __restrict__ w,
                                              float* __restrict__ out) {
    __shared__ float xs[DIM][256];
    int t = threadIdx.x;
    int p0 = blockIdx.x * 256;
#pragma unroll
    for (int c = 0; c < DIM; c++) xs[c][t] = g_fold[c * HW + p0 + t];
    __syncthreads();
    for (int o = 0; o < DIM; o++) {
        float acc = 0.f;
#pragma unroll
        for (int c = 0; c < DIM; c++) acc += __ldg(&w[o * DIM + c]) * xs[c][t];
        out[o * HW + p0 + t] = acc;
    }
}

// ============================================================================
extern "C" void kernel_launch(void* const* d_in, const int* in_sizes, int n_in,
                              void* d_out, int out_size) {
    const float* x      = (const float*)d_in[0];
    const float* w_qkv  = (const float*)d_in[1];
    const float* w_dw   = (const float*)d_in[2];
    const float* temp   = (const float*)d_in[3];
    const float* w_proj = (const float*)d_in[4];
    float* out = (float*)d_out;

    cudaFuncSetAttribute(k_gemm_qk, cudaFuncAttributeMaxDynamicSharedMemorySize,
                         2 * 128 * SA1 * 2);

    k_qkv_proj<<<HW / 256, 256>>>(x, w_qkv);
    k_dwconv<<<(QKVC * HW) / 256, 256>>>(w_dw);
    k_unfold_qk<<<(2 * NH * NP * HC) / 256, 256>>>();
    k_unfold_v<<<(NH * HC * NP) / 256, 256>>>();
    k_l2norm<<<(2 * NH * NP) / 8, 256>>>();
    k_zero_rowsum<<<(NH * NPP) / 256, 256>>>();
    {
        dim3 grid(NPP / 128, NPP / 128, NH);
        k_gemm_qk<<<grid, 256, 2 * 128 * SA1 * 2>>>(temp);
    }
    k_vscale<<<(NH * HC * NP) / 256, 256>>>();
    {
        dim3 grid(NPP / 64, NH);
        k_gemm_av<<<grid, 256>>>();
    }
    k_fold<<<(DIM * HW) / 256, 256>>>();
    k_proj<<<HW / 256, 256>>>(w_proj, out);
}